// round 1
// baseline (speedup 1.0000x reference)
#include <cuda_runtime.h>
#include <math.h>

#define NN 50000
#define EE 800000
#define ESL (EE + NN)
#define INCH 128
#define HD 256
#define NHEAD 4
#define ONODE 16
#define OEDGE 4

// -------- scratch (static device globals; no runtime allocation) --------
__device__ float    g_xp[NN * HD];                     // projected features per layer
__device__ float    g_h1[NN * HD];                     // layer-1 output
__device__ float    g_numer[NN * HD];                  // softmax-weighted accumulation
__device__ float    g_als[NN * NHEAD];
__device__ float    g_ald[NN * NHEAD];
__device__ unsigned g_m[NN * NHEAD];                   // ordered-uint encoded segment max
__device__ float    g_den[NN * NHEAD];
__device__ float    g_alpha[(size_t)ESL * NHEAD];      // per-edge logits (then reused)
__device__ float    g_ts[(size_t)NN * HD * OEDGE];     // h @ Wb  -> [N, 4*256]
__device__ float    g_Wbt[OEDGE * HD * HD];            // Wb transposed to [o*256+j][i]

// ordered-uint encoding for float atomicMax
__device__ __forceinline__ unsigned fenc(float f) {
    unsigned u = __float_as_uint(f);
    return (u & 0x80000000u) ? ~u : (u | 0x80000000u);
}
__device__ __forceinline__ float fdec(unsigned u) {
    return __uint_as_float((u & 0x80000000u) ? (u ^ 0x80000000u) : ~u);
}

// -------- init: zero accumulators (runs once per layer) --------
__global__ void k_init() {
    int i = blockIdx.x * blockDim.x + threadIdx.x;
    if (i < NN * HD) g_numer[i] = 0.f;
    if (i < NN * NHEAD) { g_m[i] = 0u; g_den[i] = 0.f; }
}

// -------- transpose Wb [4,256,256](o,i,j) -> Wbt [(o*256+j), i] --------
__global__ void k_wbt(const float* __restrict__ Wb) {
    int i = blockIdx.x * blockDim.x + threadIdx.x;
    if (i >= OEDGE * HD * HD) return;
    int o = i >> 16, r = i & 65535, ii = r >> 8, j = r & 255;
    g_Wbt[(o * HD + j) * HD + ii] = Wb[i];
}

// -------- fp32 tiled GEMM: C[M,N] = A[M,K] * B[N,K]^T (row-major) --------
// BM=BN=64, BK=16, 256 threads, 4x4 microtile. N % 64 == 0, K % 16 == 0.
__global__ void __launch_bounds__(256) k_gemm(const float* __restrict__ A,
                                              const float* __restrict__ B,
                                              float* __restrict__ C,
                                              int M, int N, int K) {
    __shared__ float As[16][68];
    __shared__ float Bs[16][68];
    int bm = blockIdx.y * 64, bn = blockIdx.x * 64;
    int tid = threadIdx.x;
    int tx = tid & 15, ty = tid >> 4;
    float acc[4][4] = {};
    for (int k0 = 0; k0 < K; k0 += 16) {
        int r = tid >> 2, c = (tid & 3) * 4;
        int gr = bm + r;
        float4 v = (gr < M) ? *(const float4*)(A + (size_t)gr * K + k0 + c)
                            : make_float4(0.f, 0.f, 0.f, 0.f);
        As[c + 0][r] = v.x; As[c + 1][r] = v.y; As[c + 2][r] = v.z; As[c + 3][r] = v.w;
        int gb = bn + r;
        float4 w = *(const float4*)(B + (size_t)gb * K + k0 + c);
        Bs[c + 0][r] = w.x; Bs[c + 1][r] = w.y; Bs[c + 2][r] = w.z; Bs[c + 3][r] = w.w;
        __syncthreads();
#pragma unroll
        for (int k = 0; k < 16; k++) {
            float a[4], b[4];
#pragma unroll
            for (int i = 0; i < 4; i++) a[i] = As[k][ty * 4 + i];
#pragma unroll
            for (int j = 0; j < 4; j++) b[j] = Bs[k][tx * 4 + j];
#pragma unroll
            for (int i = 0; i < 4; i++)
#pragma unroll
                for (int j = 0; j < 4; j++) acc[i][j] += a[i] * b[j];
        }
        __syncthreads();
    }
#pragma unroll
    for (int i = 0; i < 4; i++) {
        int gm = bm + ty * 4 + i;
        if (gm >= M) continue;
        *(float4*)(C + (size_t)gm * N + bn + tx * 4) =
            make_float4(acc[i][0], acc[i][1], acc[i][2], acc[i][3]);
    }
}

// -------- attention logits: als/ald[n,h] = sum_k xp[n,h*64+k] * a[h*64+k] --------
__global__ void k_attn(const float* __restrict__ as_, const float* __restrict__ ad_) {
    int n = blockIdx.x;
    int c = threadIdx.x;
    __shared__ float ss[256], sd[256];
    float v = g_xp[n * HD + c];
    ss[c] = v * as_[c];
    sd[c] = v * ad_[c];
    __syncthreads();
    for (int st = 32; st >= 1; st >>= 1) {
        if ((c & 63) < st) { ss[c] += ss[c + st]; sd[c] += sd[c + st]; }
        __syncthreads();
    }
    if ((c & 63) == 0) {
        int h = c >> 6;
        g_als[n * NHEAD + h] = ss[c];
        g_ald[n * NHEAD + h] = sd[c];
    }
}

// -------- edge pass A: leaky-relu logits + segment max (ordered-uint atomicMax) ----
__global__ void k_edge_max(const int* __restrict__ ei) {
    int e = blockIdx.x * blockDim.x + threadIdx.x;
    if (e >= ESL) return;
    int s, d;
    if (e < EE) { s = ei[e]; d = ei[EE + e]; } else { s = d = e - EE; }
    float4 a = *(const float4*)(g_als + s * 4);
    float4 b = *(const float4*)(g_ald + d * 4);
    float al[4] = {a.x + b.x, a.y + b.y, a.z + b.z, a.w + b.w};
#pragma unroll
    for (int h = 0; h < 4; h++) {
        float v = al[h] > 0.f ? al[h] : 0.2f * al[h];
        al[h] = v;
        atomicMax(&g_m[d * 4 + h], fenc(v));
    }
    *(float4*)(g_alpha + (size_t)e * 4) = make_float4(al[0], al[1], al[2], al[3]);
}

// -------- edge pass B: ex, den, and weighted scatter (warp per edge) --------
__global__ void k_edge_acc(const int* __restrict__ ei) {
    int t = blockIdx.x * blockDim.x + threadIdx.x;
    int e = t >> 5, lane = t & 31;
    if (e >= ESL) return;
    int s, d;
    if (e < EE) { s = __ldg(ei + e); d = __ldg(ei + EE + e); } else { s = d = e - EE; }
    int head = lane >> 3;
    float a = g_alpha[(size_t)e * 4 + head];
    float m = fdec(g_m[d * 4 + head]);
    float ex = expf(a - m);
    if ((lane & 7) == 0) atomicAdd(&g_den[d * 4 + head], ex);
    const float4* xs = (const float4*)(g_xp + (size_t)s * HD) + lane * 2;
    float4 v0 = xs[0], v1 = xs[1];
    float* nb = g_numer + (size_t)d * HD + lane * 8;
    atomicAdd(nb + 0, ex * v0.x);
    atomicAdd(nb + 1, ex * v0.y);
    atomicAdd(nb + 2, ex * v0.z);
    atomicAdd(nb + 3, ex * v0.w);
    atomicAdd(nb + 4, ex * v1.x);
    atomicAdd(nb + 5, ex * v1.y);
    atomicAdd(nb + 6, ex * v1.z);
    atomicAdd(nb + 7, ex * v1.w);
}

// -------- finalize: h = elu(numer/den + bias) --------
__global__ void k_fin(const float* __restrict__ bias, float* __restrict__ out) {
    int i = blockIdx.x * blockDim.x + threadIdx.x;
    if (i >= NN * HD) return;
    int n = i >> 8, c = i & 255, h = c >> 6;
    float v = g_numer[i] / (g_den[n * 4 + h] + 1e-16f) + bias[c];
    out[i] = v > 0.f ? v : expm1f(v);
}

// -------- node head: out[n,o] = h[n,:] . Wn[o,:] + bn[o] --------
__global__ void __launch_bounds__(256) k_nodepred(const float* __restrict__ h,
                                                  const float* __restrict__ Wn,
                                                  const float* __restrict__ bn,
                                                  float* __restrict__ out) {
    __shared__ float sh[16][260];
    __shared__ float sw[16][260];
    int nb = blockIdx.x * 16;
    for (int i = threadIdx.x; i < 16 * 256; i += 256) {
        int r = i >> 8, c = i & 255;
        sw[r][c] = Wn[i];
        int gn = nb + r;
        sh[r][c] = (gn < NN) ? h[(size_t)gn * HD + c] : 0.f;
    }
    __syncthreads();
    int i = threadIdx.x >> 4, o = threadIdx.x & 15;
    float s = 0.f;
#pragma unroll 8
    for (int k = 0; k < 256; k++) s += sh[i][k] * sw[o][k];
    int gn = nb + i;
    if (gn < NN) out[(size_t)gn * ONODE + o] = s + bn[o];
}

// -------- edge head: out[e,o] = ts[src, o*256+:] . h[dst,:] + bb[o] (warp/edge) ----
__global__ void k_bilin(const int* __restrict__ ei, const float* __restrict__ h,
                        const float* __restrict__ bb, float* __restrict__ out) {
    int t = blockIdx.x * blockDim.x + threadIdx.x;
    int e = t >> 5, lane = t & 31;
    if (e >= EE) return;
    int s = __ldg(ei + e), d = __ldg(ei + EE + e);
    const float4* hv = (const float4*)(h + (size_t)d * HD);
    float4 d0 = hv[lane], d1 = hv[lane + 32];
    float res[4];
#pragma unroll
    for (int o = 0; o < 4; o++) {
        const float4* tv = (const float4*)(g_ts + (size_t)s * (HD * OEDGE) + o * HD);
        float4 t0 = tv[lane], t1 = tv[lane + 32];
        float sum = t0.x * d0.x + t0.y * d0.y + t0.z * d0.z + t0.w * d0.w +
                    t1.x * d1.x + t1.y * d1.y + t1.z * d1.z + t1.w * d1.w;
#pragma unroll
        for (int off = 16; off; off >>= 1) sum += __shfl_down_sync(0xffffffffu, sum, off);
        res[o] = sum;
    }
    if (lane == 0) {
        *(float4*)(out + (size_t)e * 4) =
            make_float4(res[0] + bb[0], res[1] + bb[1], res[2] + bb[2], res[3] + bb[3]);
    }
}

extern "C" void kernel_launch(void* const* d_in, const int* in_sizes, int n_in,
                              void* d_out, int out_size) {
    const float* x   = (const float*)d_in[0];
    const int*   ei  = (const int*)d_in[1];
    const float* W1  = (const float*)d_in[2];
    const float* as1 = (const float*)d_in[3];
    const float* ad1 = (const float*)d_in[4];
    const float* b1  = (const float*)d_in[5];
    const float* W2  = (const float*)d_in[6];
    const float* as2 = (const float*)d_in[7];
    const float* ad2 = (const float*)d_in[8];
    const float* b2  = (const float*)d_in[9];
    const float* Wn  = (const float*)d_in[10];
    const float* bn  = (const float*)d_in[11];
    const float* Wb  = (const float*)d_in[12];
    const float* bb  = (const float*)d_in[13];

    float* out      = (float*)d_out;
    float* out_node = out;                                   // [N, 16]
    float* out_edge = out + (size_t)NN * ONODE;              // [E, 4]
    float* out_h    = out_edge + (size_t)EE * OEDGE;         // [N, 256]

    void *p_xp, *p_h1, *p_ts, *p_wbt;
    cudaGetSymbolAddress(&p_xp, g_xp);
    cudaGetSymbolAddress(&p_h1, g_h1);
    cudaGetSymbolAddress(&p_ts, g_ts);
    cudaGetSymbolAddress(&p_wbt, g_Wbt);

    const int TB = 256;
    dim3 gProj(HD / 64, (NN + 63) / 64);                     // 256-wide GEMMs
    dim3 gTs(1024 / 64, (NN + 63) / 64);                     // ts GEMM
    int gInit = (NN * HD + TB - 1) / TB;
    int gEdge1 = (ESL + TB - 1) / TB;
    int gEdgeW = ((size_t)ESL * 32 + TB - 1) / TB;

    k_wbt<<<(OEDGE * HD * HD + TB - 1) / TB, TB>>>(Wb);

    // ---- layer 1 ----
    k_init<<<gInit, TB>>>();
    k_gemm<<<gProj, TB>>>(x, W1, (float*)p_xp, NN, HD, INCH);
    k_attn<<<NN, TB>>>(as1, ad1);
    k_edge_max<<<gEdge1, TB>>>(ei);
    k_edge_acc<<<gEdgeW, TB>>>(ei);
    k_fin<<<gInit, TB>>>(b1, (float*)p_h1);

    // ---- layer 2 ----
    k_init<<<gInit, TB>>>();
    k_gemm<<<gProj, TB>>>((const float*)p_h1, W2, (float*)p_xp, NN, HD, HD);
    k_attn<<<NN, TB>>>(as2, ad2);
    k_edge_max<<<gEdge1, TB>>>(ei);
    k_edge_acc<<<gEdgeW, TB>>>(ei);
    k_fin<<<gInit, TB>>>(b2, out_h);

    // ---- heads ----
    k_nodepred<<<(NN + 15) / 16, TB>>>(out_h, Wn, bn, out_node);
    k_gemm<<<gTs, TB>>>(out_h, (const float*)p_wbt, (float*)p_ts, NN, 1024, HD);
    k_bilin<<<((size_t)EE * 32 + TB - 1) / TB, TB>>>(ei, out_h, bb, out_edge);
}

// round 2
// speedup vs baseline: 2.8966x; 2.8966x over previous
#include <cuda_runtime.h>
#include <math.h>

#define NN 50000
#define EE 800000
#define INCH 128
#define HD 256
#define NHEAD 4
#define ONODE 16
#define OEDGE 4
#define SCAN_B 196                      // ceil(NN/256)

// -------- scratch (static device globals) --------
__device__ float g_xp[NN * HD];         // projected features per layer
__device__ float g_h1[NN * HD];         // layer-1 output
__device__ float g_als[NN * NHEAD];
__device__ float g_ald[NN * NHEAD];
__device__ float g_ts[(size_t)NN * HD * OEDGE];   // td = h @ Wb  -> [N, 4*256]
__device__ int   g_cnt[NN];             // histogram, then scatter cursor
__device__ int   g_off2[NN + 1];        // CSR offsets (dst-sorted)
__device__ int   g_bsum[256];
__device__ int   g_srcs[EE];            // src per dst-sorted edge
__device__ int   g_eids[EE];            // original edge id per dst-sorted edge

// ================= counting sort by dst =================
__global__ void k_zero() {
    int i = blockIdx.x * blockDim.x + threadIdx.x;
    if (i < NN) g_cnt[i] = 0;
}
__global__ void k_hist(const int* __restrict__ ei) {
    int e = blockIdx.x * blockDim.x + threadIdx.x;
    if (e < EE) atomicAdd(&g_cnt[ei[EE + e]], 1);
}
__global__ void k_scan1() {
    __shared__ int s[256];
    int t = threadIdx.x, i = blockIdx.x * 256 + t;
    int v = (i < NN) ? g_cnt[i] : 0;
    s[t] = v;
    __syncthreads();
    for (int st = 1; st < 256; st <<= 1) {
        int x = (t >= st) ? s[t - st] : 0;
        __syncthreads();
        s[t] += x;
        __syncthreads();
    }
    if (i < NN) g_off2[i] = s[t] - v;           // exclusive (local)
    if (t == 255) g_bsum[blockIdx.x] = s[255];
}
__global__ void k_scan2() {
    __shared__ int s[256];
    int t = threadIdx.x;
    int v = (t < SCAN_B) ? g_bsum[t] : 0;
    s[t] = v;
    __syncthreads();
    for (int st = 1; st < 256; st <<= 1) {
        int x = (t >= st) ? s[t - st] : 0;
        __syncthreads();
        s[t] += x;
        __syncthreads();
    }
    if (t < SCAN_B) g_bsum[t] = s[t] - v;       // exclusive
}
__global__ void k_scan3() {
    int i = blockIdx.x * blockDim.x + threadIdx.x;
    if (i < NN) {
        int v = g_off2[i] + g_bsum[i >> 8];
        g_off2[i] = v;
        g_cnt[i] = v;                           // scatter cursor
    }
    if (i == 0) g_off2[NN] = EE;
}
__global__ void k_scatter(const int* __restrict__ ei) {
    int e = blockIdx.x * blockDim.x + threadIdx.x;
    if (e >= EE) return;
    int d = ei[EE + e];
    int pos = atomicAdd(&g_cnt[d], 1);
    g_srcs[pos] = ei[e];
    g_eids[pos] = e;
}

// ================= SGEMM: C[M,N] = A[M,K] * B[N,K]^T =================
// 128x128x8 tiles, 256 threads, 8x8 microtile, double-buffered smem.
// Requires N % 128 == 0, K % 8 == 0; M arbitrary.
__global__ void __launch_bounds__(256) k_gemm(const float* __restrict__ A,
                                              const float* __restrict__ B,
                                              float* __restrict__ C,
                                              int M, int N, int K) {
    __shared__ float As[2][8][132];
    __shared__ float Bs[2][8][132];
    const int bm = blockIdx.y * 128, bn = blockIdx.x * 128;
    const int tid = threadIdx.x;
    const int lr = tid >> 1;
    const int lc = (tid & 1) << 2;
    const int arow = bm + lr;
    const bool aok = arow < M;
    const float* Ap = A + (size_t)(aok ? arow : (M - 1)) * K + lc;
    const float* Bp = B + (size_t)(bn + lr) * K + lc;

    float4 av = aok ? *(const float4*)Ap : make_float4(0.f, 0.f, 0.f, 0.f);
    float4 bv = *(const float4*)Bp;
    As[0][lc + 0][lr] = av.x; As[0][lc + 1][lr] = av.y;
    As[0][lc + 2][lr] = av.z; As[0][lc + 3][lr] = av.w;
    Bs[0][lc + 0][lr] = bv.x; Bs[0][lc + 1][lr] = bv.y;
    Bs[0][lc + 2][lr] = bv.z; Bs[0][lc + 3][lr] = bv.w;
    __syncthreads();

    const int tx = (tid & 15) << 3;
    const int ty = (tid >> 4) << 3;
    float acc[8][8] = {};
    const int nk = K >> 3;
    for (int t = 0; t < nk; t++) {
        const int cur = t & 1;
        if (t + 1 < nk) {
            av = aok ? *(const float4*)(Ap + (size_t)(t + 1) * 8)
                     : make_float4(0.f, 0.f, 0.f, 0.f);
            bv = *(const float4*)(Bp + (size_t)(t + 1) * 8);
        }
#pragma unroll
        for (int k = 0; k < 8; k++) {
            float a[8], b[8];
            *(float4*)(a)     = *(const float4*)&As[cur][k][ty];
            *(float4*)(a + 4) = *(const float4*)&As[cur][k][ty + 4];
            *(float4*)(b)     = *(const float4*)&Bs[cur][k][tx];
            *(float4*)(b + 4) = *(const float4*)&Bs[cur][k][tx + 4];
#pragma unroll
            for (int i = 0; i < 8; i++)
#pragma unroll
                for (int j = 0; j < 8; j++)
                    acc[i][j] += a[i] * b[j];
        }
        if (t + 1 < nk) {
            const int nxt = cur ^ 1;
            As[nxt][lc + 0][lr] = av.x; As[nxt][lc + 1][lr] = av.y;
            As[nxt][lc + 2][lr] = av.z; As[nxt][lc + 3][lr] = av.w;
            Bs[nxt][lc + 0][lr] = bv.x; Bs[nxt][lc + 1][lr] = bv.y;
            Bs[nxt][lc + 2][lr] = bv.z; Bs[nxt][lc + 3][lr] = bv.w;
            __syncthreads();
        }
    }
#pragma unroll
    for (int i = 0; i < 8; i++) {
        int gm = bm + ty + i;
        if (gm < M) {
            *(float4*)(C + (size_t)gm * N + bn + tx) =
                make_float4(acc[i][0], acc[i][1], acc[i][2], acc[i][3]);
            *(float4*)(C + (size_t)gm * N + bn + tx + 4) =
                make_float4(acc[i][4], acc[i][5], acc[i][6], acc[i][7]);
        }
    }
}

// ============ attention logits: warp per node ============
__global__ void k_attn(const float* __restrict__ xp, const float* __restrict__ as_,
                       const float* __restrict__ ad_) {
    int t = blockIdx.x * blockDim.x + threadIdx.x;
    int n = t >> 5, l = t & 31;
    if (n >= NN) return;
    const float4* xr = (const float4*)xp + (size_t)n * 64 + l * 2;
    float4 v0 = xr[0], v1 = xr[1];
    const float4* ar = (const float4*)as_ + l * 2;
    const float4* dr = (const float4*)ad_ + l * 2;
    float4 a0 = __ldg(ar), a1 = __ldg(ar + 1);
    float4 b0 = __ldg(dr), b1 = __ldg(dr + 1);
    float ss = v0.x * a0.x + v0.y * a0.y + v0.z * a0.z + v0.w * a0.w +
               v1.x * a1.x + v1.y * a1.y + v1.z * a1.z + v1.w * a1.w;
    float sd = v0.x * b0.x + v0.y * b0.y + v0.z * b0.z + v0.w * b0.w +
               v1.x * b1.x + v1.y * b1.y + v1.z * b1.z + v1.w * b1.w;
#pragma unroll
    for (int o = 4; o; o >>= 1) {
        ss += __shfl_xor_sync(0xffffffffu, ss, o);
        sd += __shfl_xor_sync(0xffffffffu, sd, o);
    }
    if ((l & 7) == 0) {
        int h = l >> 3;
        g_als[n * NHEAD + h] = ss;
        g_ald[n * NHEAD + h] = sd;
    }
}

__device__ __forceinline__ float lrelu(float v) { return v > 0.f ? v : 0.2f * v; }

// ============ fused GAT aggregation: warp per dst node ============
// pass1: per-head max over incoming edges (+ self loop); pass2: exp/den/accumulate;
// finalize h = elu(agg/den + bias). No atomics.
__global__ void k_gat(const float* __restrict__ xp, const float* __restrict__ bias,
                      float* __restrict__ hout) {
    int t = blockIdx.x * blockDim.x + threadIdx.x;
    int d = t >> 5, lane = t & 31;
    if (d >= NN) return;
    int h = lane >> 3;
    float4 d4 = __ldg((const float4*)g_ald + d);
    float4 sa4 = __ldg((const float4*)g_als + d);
    float m0 = lrelu(sa4.x + d4.x), m1 = lrelu(sa4.y + d4.y);
    float m2 = lrelu(sa4.z + d4.z), m3 = lrelu(sa4.w + d4.w);
    int beg = g_off2[d], end = g_off2[d + 1];
    for (int p = beg + lane; p < end; p += 32) {
        int s = g_srcs[p];
        float4 a = __ldg((const float4*)g_als + s);
        m0 = fmaxf(m0, lrelu(a.x + d4.x));
        m1 = fmaxf(m1, lrelu(a.y + d4.y));
        m2 = fmaxf(m2, lrelu(a.z + d4.z));
        m3 = fmaxf(m3, lrelu(a.w + d4.w));
    }
#pragma unroll
    for (int o = 16; o; o >>= 1) {
        m0 = fmaxf(m0, __shfl_xor_sync(0xffffffffu, m0, o));
        m1 = fmaxf(m1, __shfl_xor_sync(0xffffffffu, m1, o));
        m2 = fmaxf(m2, __shfl_xor_sync(0xffffffffu, m2, o));
        m3 = fmaxf(m3, __shfl_xor_sync(0xffffffffu, m3, o));
    }
    float mh   = h == 0 ? m0 : h == 1 ? m1 : h == 2 ? m2 : m3;
    float aldh = h == 0 ? d4.x : h == 1 ? d4.y : h == 2 ? d4.z : d4.w;
    float acc[8] = {};
    float den = 0.f;
    const float4* xpv = (const float4*)xp;
    {   // self loop
        float ash = h == 0 ? sa4.x : h == 1 ? sa4.y : h == 2 ? sa4.z : sa4.w;
        float ex = __expf(lrelu(ash + aldh) - mh);
        den += ex;
        float4 v0 = __ldg(xpv + (size_t)d * 64 + lane * 2);
        float4 v1 = __ldg(xpv + (size_t)d * 64 + lane * 2 + 1);
        acc[0] += ex * v0.x; acc[1] += ex * v0.y; acc[2] += ex * v0.z; acc[3] += ex * v0.w;
        acc[4] += ex * v1.x; acc[5] += ex * v1.y; acc[6] += ex * v1.z; acc[7] += ex * v1.w;
    }
    for (int p = beg; p < end; p++) {
        int s = g_srcs[p];
        float ash = __ldg(g_als + (size_t)s * 4 + h);
        float ex = __expf(lrelu(ash + aldh) - mh);
        den += ex;
        float4 v0 = __ldg(xpv + (size_t)s * 64 + lane * 2);
        float4 v1 = __ldg(xpv + (size_t)s * 64 + lane * 2 + 1);
        acc[0] += ex * v0.x; acc[1] += ex * v0.y; acc[2] += ex * v0.z; acc[3] += ex * v0.w;
        acc[4] += ex * v1.x; acc[5] += ex * v1.y; acc[6] += ex * v1.z; acc[7] += ex * v1.w;
    }
    float inv = 1.f / (den + 1e-16f);
    const float4* bv4 = (const float4*)bias;
    float4 b0 = __ldg(bv4 + lane * 2), b1 = __ldg(bv4 + lane * 2 + 1);
    float r[8];
    r[0] = acc[0] * inv + b0.x; r[1] = acc[1] * inv + b0.y;
    r[2] = acc[2] * inv + b0.z; r[3] = acc[3] * inv + b0.w;
    r[4] = acc[4] * inv + b1.x; r[5] = acc[5] * inv + b1.y;
    r[6] = acc[6] * inv + b1.z; r[7] = acc[7] * inv + b1.w;
#pragma unroll
    for (int j = 0; j < 8; j++) r[j] = r[j] > 0.f ? r[j] : expm1f(r[j]);
    float4* ho = (float4*)hout + (size_t)d * 64 + lane * 2;
    ho[0] = make_float4(r[0], r[1], r[2], r[3]);
    ho[1] = make_float4(r[4], r[5], r[6], r[7]);
}

// ============ node head ============
__global__ void __launch_bounds__(256) k_nodepred(const float* __restrict__ h,
                                                  const float* __restrict__ Wn,
                                                  const float* __restrict__ bn,
                                                  float* __restrict__ out) {
    __shared__ float sh[16][260];
    __shared__ float sw[16][260];
    int nb = blockIdx.x * 16;
    for (int i = threadIdx.x; i < 16 * 256; i += 256) {
        int r = i >> 8, c = i & 255;
        sw[r][c] = Wn[i];
        int gn = nb + r;
        sh[r][c] = (gn < NN) ? h[(size_t)gn * HD + c] : 0.f;
    }
    __syncthreads();
    int i = threadIdx.x >> 4, o = threadIdx.x & 15;
    float s = 0.f;
#pragma unroll 8
    for (int k = 0; k < 256; k++) s += sh[i][k] * sw[o][k];
    int gn = nb + i;
    if (gn < NN) out[(size_t)gn * ONODE + o] = s + bn[o];
}

// ============ edge head: warp per dst, td row cached in registers ============
// out[e,o] = h[src] . td[dst, o*256 + :] + bb[o]
__global__ void k_bilin(const float* __restrict__ h, const float* __restrict__ bb,
                        float* __restrict__ out) {
    int t = blockIdx.x * blockDim.x + threadIdx.x;
    int d = t >> 5, lane = t & 31;
    if (d >= NN) return;
    const float4* tdv = (const float4*)(g_ts + (size_t)d * 1024);
    float4 t0[4], t1[4];
#pragma unroll
    for (int o = 0; o < 4; o++) {
        t0[o] = __ldg(tdv + o * 64 + lane * 2);
        t1[o] = __ldg(tdv + o * 64 + lane * 2 + 1);
    }
    float4 bbv = __ldg((const float4*)bb);
    const float4* hv = (const float4*)h;
    int beg = g_off2[d], end = g_off2[d + 1];
    for (int p = beg; p < end; p++) {
        int s = g_srcs[p];
        float4 h0 = __ldg(hv + (size_t)s * 64 + lane * 2);
        float4 h1 = __ldg(hv + (size_t)s * 64 + lane * 2 + 1);
        float s0 = t0[0].x * h0.x + t0[0].y * h0.y + t0[0].z * h0.z + t0[0].w * h0.w +
                   t1[0].x * h1.x + t1[0].y * h1.y + t1[0].z * h1.z + t1[0].w * h1.w;
        float s1 = t0[1].x * h0.x + t0[1].y * h0.y + t0[1].z * h0.z + t0[1].w * h0.w +
                   t1[1].x * h1.x + t1[1].y * h1.y + t1[1].z * h1.z + t1[1].w * h1.w;
        float s2 = t0[2].x * h0.x + t0[2].y * h0.y + t0[2].z * h0.z + t0[2].w * h0.w +
                   t1[2].x * h1.x + t1[2].y * h1.y + t1[2].z * h1.z + t1[2].w * h1.w;
        float s3 = t0[3].x * h0.x + t0[3].y * h0.y + t0[3].z * h0.z + t0[3].w * h0.w +
                   t1[3].x * h1.x + t1[3].y * h1.y + t1[3].z * h1.z + t1[3].w * h1.w;
#pragma unroll
        for (int o = 16; o; o >>= 1) {
            s0 += __shfl_down_sync(0xffffffffu, s0, o);
            s1 += __shfl_down_sync(0xffffffffu, s1, o);
            s2 += __shfl_down_sync(0xffffffffu, s2, o);
            s3 += __shfl_down_sync(0xffffffffu, s3, o);
        }
        if (lane == 0) {
            int e = g_eids[p];
            *(float4*)(out + (size_t)e * 4) =
                make_float4(s0 + bbv.x, s1 + bbv.y, s2 + bbv.z, s3 + bbv.w);
        }
    }
}

extern "C" void kernel_launch(void* const* d_in, const int* in_sizes, int n_in,
                              void* d_out, int out_size) {
    const float* x   = (const float*)d_in[0];
    const int*   ei  = (const int*)d_in[1];
    const float* W1  = (const float*)d_in[2];
    const float* as1 = (const float*)d_in[3];
    const float* ad1 = (const float*)d_in[4];
    const float* b1  = (const float*)d_in[5];
    const float* W2  = (const float*)d_in[6];
    const float* as2 = (const float*)d_in[7];
    const float* ad2 = (const float*)d_in[8];
    const float* b2  = (const float*)d_in[9];
    const float* Wn  = (const float*)d_in[10];
    const float* bn  = (const float*)d_in[11];
    const float* Wb  = (const float*)d_in[12];
    const float* bb  = (const float*)d_in[13];

    float* out      = (float*)d_out;
    float* out_node = out;                                   // [N, 16]
    float* out_edge = out + (size_t)NN * ONODE;              // [E, 4]
    float* out_h    = out_edge + (size_t)EE * OEDGE;         // [N, 256]

    void *p_xp, *p_h1, *p_ts;
    cudaGetSymbolAddress(&p_xp, g_xp);
    cudaGetSymbolAddress(&p_h1, g_h1);
    cudaGetSymbolAddress(&p_ts, g_ts);

    const int TB = 256;
    dim3 gProj(HD / 128, (NN + 127) / 128);                  // 2 x 391
    dim3 gTd(1024 / 128, (NN + 127) / 128);                  // 8 x 391
    int gNode = (NN + TB - 1) / TB;
    int gEdge = (EE + TB - 1) / TB;
    int gWarpN = (NN * 32 + TB - 1) / TB;                    // warp-per-node grids

    // ---- build dst-sorted CSR (once per launch) ----
    k_zero<<<gNode, TB>>>();
    k_hist<<<gEdge, TB>>>(ei);
    k_scan1<<<SCAN_B, 256>>>();
    k_scan2<<<1, 256>>>();
    k_scan3<<<gNode, TB>>>();
    k_scatter<<<gEdge, TB>>>(ei);

    // ---- layer 1 ----
    k_gemm<<<gProj, TB>>>(x, W1, (float*)p_xp, NN, HD, INCH);
    k_attn<<<gWarpN, TB>>>((const float*)p_xp, as1, ad1);
    k_gat<<<gWarpN, TB>>>((const float*)p_xp, b1, (float*)p_h1);

    // ---- layer 2 ----
    k_gemm<<<gProj, TB>>>((const float*)p_h1, W2, (float*)p_xp, NN, HD, HD);
    k_attn<<<gWarpN, TB>>>((const float*)p_xp, as2, ad2);
    k_gat<<<gWarpN, TB>>>((const float*)p_xp, b2, out_h);

    // ---- heads ----
    k_nodepred<<<(NN + 15) / 16, TB>>>(out_h, Wn, bn, out_node);
    k_gemm<<<gTd, TB>>>(out_h, Wb, (float*)p_ts, NN, 1024, HD);   // td = h @ Wb^T (Wb as [1024,256])
    k_bilin<<<gWarpN, TB>>>(out_h, bb, out_edge);
}

// round 3
// speedup vs baseline: 5.2480x; 1.8118x over previous
#include <cuda_runtime.h>
#include <math.h>
#include <stdint.h>

#define NN 50000
#define EE 800000
#define INCH 128
#define HD 256
#define NHEAD 4
#define ONODE 16
#define OEDGE 4
#define SCAN_B 196                      // ceil(NN/256)

// -------- scratch (static device globals) --------
__device__ float g_xp[NN * HD];         // projected features per layer
__device__ float g_h1[NN * HD];         // layer-1 output
__device__ float g_als[NN * NHEAD];
__device__ float g_ald[NN * NHEAD];
__device__ float g_ts[(size_t)NN * HD * OEDGE];   // td = h @ Wb  -> [N, 4*256]
__device__ int   g_cnt[NN];             // histogram, then scatter cursor
__device__ int   g_off2[NN + 1];        // CSR offsets (dst-sorted)
__device__ int   g_bsum[256];
__device__ int   g_srcs[EE];            // src per dst-sorted edge
__device__ int   g_eids[EE];            // original edge id per dst-sorted edge

// ================= counting sort by dst =================
__global__ void k_zero() {
    int i = blockIdx.x * blockDim.x + threadIdx.x;
    if (i < NN) g_cnt[i] = 0;
}
__global__ void k_hist(const int* __restrict__ ei) {
    int e = blockIdx.x * blockDim.x + threadIdx.x;
    if (e < EE) atomicAdd(&g_cnt[ei[EE + e]], 1);
}
__global__ void k_scan1() {
    __shared__ int s[256];
    int t = threadIdx.x, i = blockIdx.x * 256 + t;
    int v = (i < NN) ? g_cnt[i] : 0;
    s[t] = v;
    __syncthreads();
    for (int st = 1; st < 256; st <<= 1) {
        int x = (t >= st) ? s[t - st] : 0;
        __syncthreads();
        s[t] += x;
        __syncthreads();
    }
    if (i < NN) g_off2[i] = s[t] - v;           // exclusive (local)
    if (t == 255) g_bsum[blockIdx.x] = s[255];
}
__global__ void k_scan2() {
    __shared__ int s[256];
    int t = threadIdx.x;
    int v = (t < SCAN_B) ? g_bsum[t] : 0;
    s[t] = v;
    __syncthreads();
    for (int st = 1; st < 256; st <<= 1) {
        int x = (t >= st) ? s[t - st] : 0;
        __syncthreads();
        s[t] += x;
        __syncthreads();
    }
    if (t < SCAN_B) g_bsum[t] = s[t] - v;       // exclusive
}
__global__ void k_scan3() {
    int i = blockIdx.x * blockDim.x + threadIdx.x;
    if (i < NN) {
        int v = g_off2[i] + g_bsum[i >> 8];
        g_off2[i] = v;
        g_cnt[i] = v;                           // scatter cursor
    }
    if (i == 0) g_off2[NN] = EE;
}
__global__ void k_scatter(const int* __restrict__ ei) {
    int e = blockIdx.x * blockDim.x + threadIdx.x;
    if (e >= EE) return;
    int d = ei[EE + e];
    int pos = atomicAdd(&g_cnt[d], 1);
    g_srcs[pos] = ei[e];
    g_eids[pos] = e;
}

// ================= tf32 tensor-core GEMM: C[M,N] = A[M,K] * B[N,K]^T ============
// Block 128x128x32, 256 threads (8 warps), warp tile 32x64 via mma.m16n8k8.tf32.
// Requires N % 128 == 0, K % 32 == 0; M arbitrary.
__device__ __forceinline__ uint32_t f2tf32(float f) {
    uint32_t r;
    asm("cvt.rna.tf32.f32 %0, %1;" : "=r"(r) : "f"(f));
    return r;
}

__global__ void __launch_bounds__(256) k_gemm_tc(const float* __restrict__ A,
                                                 const float* __restrict__ B,
                                                 float* __restrict__ C,
                                                 int M, int N, int K) {
    __shared__ uint32_t As[128][36];
    __shared__ uint32_t Bs[128][36];
    const int bm = blockIdx.y * 128, bn = blockIdx.x * 128;
    const int tid = threadIdx.x;
    const int wid = tid >> 5, lane = tid & 31;
    const int wm = (wid & 3) * 32;          // warp m offset in tile
    const int wn = (wid >> 2) * 64;         // warp n offset in tile
    const int g = lane >> 2, t = lane & 3;  // fragment row-group / thread-in-group

    const int r = tid >> 3;                 // copy row (0..31)
    const int c4 = (tid & 7) * 4;           // copy col (float4)

    float acc[2][8][4];
#pragma unroll
    for (int i = 0; i < 2; i++)
#pragma unroll
        for (int j = 0; j < 8; j++)
#pragma unroll
            for (int q = 0; q < 4; q++) acc[i][j][q] = 0.f;

    for (int k0 = 0; k0 < K; k0 += 32) {
        if (k0) __syncthreads();
#pragma unroll
        for (int i = 0; i < 4; i++) {
            int ar = bm + r + i * 32;
            ar = ar < M ? ar : M - 1;
            float4 v = *(const float4*)(A + (size_t)ar * K + k0 + c4);
            As[r + i * 32][c4 + 0] = f2tf32(v.x);
            As[r + i * 32][c4 + 1] = f2tf32(v.y);
            As[r + i * 32][c4 + 2] = f2tf32(v.z);
            As[r + i * 32][c4 + 3] = f2tf32(v.w);
            int br = bn + r + i * 32;
            float4 w = *(const float4*)(B + (size_t)br * K + k0 + c4);
            Bs[r + i * 32][c4 + 0] = f2tf32(w.x);
            Bs[r + i * 32][c4 + 1] = f2tf32(w.y);
            Bs[r + i * 32][c4 + 2] = f2tf32(w.z);
            Bs[r + i * 32][c4 + 3] = f2tf32(w.w);
        }
        __syncthreads();
#pragma unroll
        for (int kk = 0; kk < 32; kk += 8) {
            uint32_t a[2][4], b[8][2];
#pragma unroll
            for (int mi = 0; mi < 2; mi++) {
                int rb = wm + mi * 16;
                a[mi][0] = As[rb + g][kk + t];
                a[mi][1] = As[rb + g + 8][kk + t];
                a[mi][2] = As[rb + g][kk + t + 4];
                a[mi][3] = As[rb + g + 8][kk + t + 4];
            }
#pragma unroll
            for (int ni = 0; ni < 8; ni++) {
                int nb = wn + ni * 8;
                b[ni][0] = Bs[nb + g][kk + t];
                b[ni][1] = Bs[nb + g][kk + t + 4];
            }
#pragma unroll
            for (int mi = 0; mi < 2; mi++)
#pragma unroll
                for (int ni = 0; ni < 8; ni++) {
                    asm("mma.sync.aligned.m16n8k8.row.col.f32.tf32.tf32.f32 "
                        "{%0,%1,%2,%3}, {%4,%5,%6,%7}, {%8,%9}, {%0,%1,%2,%3};"
                        : "+f"(acc[mi][ni][0]), "+f"(acc[mi][ni][1]),
                          "+f"(acc[mi][ni][2]), "+f"(acc[mi][ni][3])
                        : "r"(a[mi][0]), "r"(a[mi][1]), "r"(a[mi][2]), "r"(a[mi][3]),
                          "r"(b[ni][0]), "r"(b[ni][1]));
                }
        }
    }
#pragma unroll
    for (int mi = 0; mi < 2; mi++) {
        int row0 = bm + wm + mi * 16 + g;
#pragma unroll
        for (int ni = 0; ni < 8; ni++) {
            int col = bn + wn + ni * 8 + t * 2;
            if (row0 < M)
                *(float2*)(C + (size_t)row0 * N + col) =
                    make_float2(acc[mi][ni][0], acc[mi][ni][1]);
            if (row0 + 8 < M)
                *(float2*)(C + (size_t)(row0 + 8) * N + col) =
                    make_float2(acc[mi][ni][2], acc[mi][ni][3]);
        }
    }
}

// ============ attention logits: warp per node ============
__global__ void k_attn(const float* __restrict__ xp, const float* __restrict__ as_,
                       const float* __restrict__ ad_) {
    int t = blockIdx.x * blockDim.x + threadIdx.x;
    int n = t >> 5, l = t & 31;
    if (n >= NN) return;
    const float4* xr = (const float4*)xp + (size_t)n * 64 + l * 2;
    float4 v0 = xr[0], v1 = xr[1];
    const float4* ar = (const float4*)as_ + l * 2;
    const float4* dr = (const float4*)ad_ + l * 2;
    float4 a0 = __ldg(ar), a1 = __ldg(ar + 1);
    float4 b0 = __ldg(dr), b1 = __ldg(dr + 1);
    float ss = v0.x * a0.x + v0.y * a0.y + v0.z * a0.z + v0.w * a0.w +
               v1.x * a1.x + v1.y * a1.y + v1.z * a1.z + v1.w * a1.w;
    float sd = v0.x * b0.x + v0.y * b0.y + v0.z * b0.z + v0.w * b0.w +
               v1.x * b1.x + v1.y * b1.y + v1.z * b1.z + v1.w * b1.w;
#pragma unroll
    for (int o = 4; o; o >>= 1) {
        ss += __shfl_xor_sync(0xffffffffu, ss, o);
        sd += __shfl_xor_sync(0xffffffffu, sd, o);
    }
    if ((l & 7) == 0) {
        int h = l >> 3;
        g_als[n * NHEAD + h] = ss;
        g_ald[n * NHEAD + h] = sd;
    }
}

__device__ __forceinline__ float lrelu(float v) { return v > 0.f ? v : 0.2f * v; }

// ============ fused GAT aggregation: warp per dst node ============
__global__ void k_gat(const float* __restrict__ xp, const float* __restrict__ bias,
                      float* __restrict__ hout) {
    int t = blockIdx.x * blockDim.x + threadIdx.x;
    int d = t >> 5, lane = t & 31;
    if (d >= NN) return;
    int h = lane >> 3;
    float4 d4 = __ldg((const float4*)g_ald + d);
    float4 sa4 = __ldg((const float4*)g_als + d);
    float m0 = lrelu(sa4.x + d4.x), m1 = lrelu(sa4.y + d4.y);
    float m2 = lrelu(sa4.z + d4.z), m3 = lrelu(sa4.w + d4.w);
    int beg = g_off2[d], end = g_off2[d + 1];
    for (int p = beg + lane; p < end; p += 32) {
        int s = g_srcs[p];
        float4 a = __ldg((const float4*)g_als + s);
        m0 = fmaxf(m0, lrelu(a.x + d4.x));
        m1 = fmaxf(m1, lrelu(a.y + d4.y));
        m2 = fmaxf(m2, lrelu(a.z + d4.z));
        m3 = fmaxf(m3, lrelu(a.w + d4.w));
    }
#pragma unroll
    for (int o = 16; o; o >>= 1) {
        m0 = fmaxf(m0, __shfl_xor_sync(0xffffffffu, m0, o));
        m1 = fmaxf(m1, __shfl_xor_sync(0xffffffffu, m1, o));
        m2 = fmaxf(m2, __shfl_xor_sync(0xffffffffu, m2, o));
        m3 = fmaxf(m3, __shfl_xor_sync(0xffffffffu, m3, o));
    }
    float mh   = h == 0 ? m0 : h == 1 ? m1 : h == 2 ? m2 : m3;
    float aldh = h == 0 ? d4.x : h == 1 ? d4.y : h == 2 ? d4.z : d4.w;
    float acc[8] = {};
    float den = 0.f;
    const float4* xpv = (const float4*)xp;
    {   // self loop
        float ash = h == 0 ? sa4.x : h == 1 ? sa4.y : h == 2 ? sa4.z : sa4.w;
        float ex = __expf(lrelu(ash + aldh) - mh);
        den += ex;
        float4 v0 = __ldg(xpv + (size_t)d * 64 + lane * 2);
        float4 v1 = __ldg(xpv + (size_t)d * 64 + lane * 2 + 1);
        acc[0] += ex * v0.x; acc[1] += ex * v0.y; acc[2] += ex * v0.z; acc[3] += ex * v0.w;
        acc[4] += ex * v1.x; acc[5] += ex * v1.y; acc[6] += ex * v1.z; acc[7] += ex * v1.w;
    }
    for (int p = beg; p < end; p++) {
        int s = g_srcs[p];
        float ash = __ldg(g_als + (size_t)s * 4 + h);
        float ex = __expf(lrelu(ash + aldh) - mh);
        den += ex;
        float4 v0 = __ldg(xpv + (size_t)s * 64 + lane * 2);
        float4 v1 = __ldg(xpv + (size_t)s * 64 + lane * 2 + 1);
        acc[0] += ex * v0.x; acc[1] += ex * v0.y; acc[2] += ex * v0.z; acc[3] += ex * v0.w;
        acc[4] += ex * v1.x; acc[5] += ex * v1.y; acc[6] += ex * v1.z; acc[7] += ex * v1.w;
    }
    float inv = 1.f / (den + 1e-16f);
    const float4* bv4 = (const float4*)bias;
    float4 b0 = __ldg(bv4 + lane * 2), b1 = __ldg(bv4 + lane * 2 + 1);
    float r[8];
    r[0] = acc[0] * inv + b0.x; r[1] = acc[1] * inv + b0.y;
    r[2] = acc[2] * inv + b0.z; r[3] = acc[3] * inv + b0.w;
    r[4] = acc[4] * inv + b1.x; r[5] = acc[5] * inv + b1.y;
    r[6] = acc[6] * inv + b1.z; r[7] = acc[7] * inv + b1.w;
#pragma unroll
    for (int j = 0; j < 8; j++) r[j] = r[j] > 0.f ? r[j] : expm1f(r[j]);
    float4* ho = (float4*)hout + (size_t)d * 64 + lane * 2;
    ho[0] = make_float4(r[0], r[1], r[2], r[3]);
    ho[1] = make_float4(r[4], r[5], r[6], r[7]);
}

// ============ node head ============
__global__ void __launch_bounds__(256) k_nodepred(const float* __restrict__ h,
                                                  const float* __restrict__ Wn,
                                                  const float* __restrict__ bn,
                                                  float* __restrict__ out) {
    __shared__ float sh[16][260];
    __shared__ float sw[16][260];
    int nb = blockIdx.x * 16;
    for (int i = threadIdx.x; i < 16 * 256; i += 256) {
        int r = i >> 8, c = i & 255;
        sw[r][c] = Wn[i];
        int gn = nb + r;
        sh[r][c] = (gn < NN) ? h[(size_t)gn * HD + c] : 0.f;
    }
    __syncthreads();
    int i = threadIdx.x >> 4, o = threadIdx.x & 15;
    float s = 0.f;
#pragma unroll 8
    for (int k = 0; k < 256; k++) s += sh[i][k] * sw[o][k];
    int gn = nb + i;
    if (gn < NN) out[(size_t)gn * ONODE + o] = s + bn[o];
}

// ============ edge head: warp per dst, td row cached in registers ============
__global__ void k_bilin(const float* __restrict__ h, const float* __restrict__ bb,
                        float* __restrict__ out) {
    int t = blockIdx.x * blockDim.x + threadIdx.x;
    int d = t >> 5, lane = t & 31;
    if (d >= NN) return;
    const float4* tdv = (const float4*)(g_ts + (size_t)d * 1024);
    float4 t0[4], t1[4];
#pragma unroll
    for (int o = 0; o < 4; o++) {
        t0[o] = __ldg(tdv + o * 64 + lane * 2);
        t1[o] = __ldg(tdv + o * 64 + lane * 2 + 1);
    }
    float4 bbv = __ldg((const float4*)bb);
    const float4* hv = (const float4*)h;
    int beg = g_off2[d], end = g_off2[d + 1];
    for (int p = beg; p < end; p++) {
        int s = g_srcs[p];
        float4 h0 = __ldg(hv + (size_t)s * 64 + lane * 2);
        float4 h1 = __ldg(hv + (size_t)s * 64 + lane * 2 + 1);
        float s0 = t0[0].x * h0.x + t0[0].y * h0.y + t0[0].z * h0.z + t0[0].w * h0.w +
                   t1[0].x * h1.x + t1[0].y * h1.y + t1[0].z * h1.z + t1[0].w * h1.w;
        float s1 = t0[1].x * h0.x + t0[1].y * h0.y + t0[1].z * h0.z + t0[1].w * h0.w +
                   t1[1].x * h1.x + t1[1].y * h1.y + t1[1].z * h1.z + t1[1].w * h1.w;
        float s2 = t0[2].x * h0.x + t0[2].y * h0.y + t0[2].z * h0.z + t0[2].w * h0.w +
                   t1[2].x * h1.x + t1[2].y * h1.y + t1[2].z * h1.z + t1[2].w * h1.w;
        float s3 = t0[3].x * h0.x + t0[3].y * h0.y + t0[3].z * h0.z + t0[3].w * h0.w +
                   t1[3].x * h1.x + t1[3].y * h1.y + t1[3].z * h1.z + t1[3].w * h1.w;
#pragma unroll
        for (int o = 16; o; o >>= 1) {
            s0 += __shfl_down_sync(0xffffffffu, s0, o);
            s1 += __shfl_down_sync(0xffffffffu, s1, o);
            s2 += __shfl_down_sync(0xffffffffu, s2, o);
            s3 += __shfl_down_sync(0xffffffffu, s3, o);
        }
        if (lane == 0) {
            int e = g_eids[p];
            *(float4*)(out + (size_t)e * 4) =
                make_float4(s0 + bbv.x, s1 + bbv.y, s2 + bbv.z, s3 + bbv.w);
        }
    }
}

extern "C" void kernel_launch(void* const* d_in, const int* in_sizes, int n_in,
                              void* d_out, int out_size) {
    const float* x   = (const float*)d_in[0];
    const int*   ei  = (const int*)d_in[1];
    const float* W1  = (const float*)d_in[2];
    const float* as1 = (const float*)d_in[3];
    const float* ad1 = (const float*)d_in[4];
    const float* b1  = (const float*)d_in[5];
    const float* W2  = (const float*)d_in[6];
    const float* as2 = (const float*)d_in[7];
    const float* ad2 = (const float*)d_in[8];
    const float* b2  = (const float*)d_in[9];
    const float* Wn  = (const float*)d_in[10];
    const float* bn  = (const float*)d_in[11];
    const float* Wb  = (const float*)d_in[12];
    const float* bb  = (const float*)d_in[13];

    float* out      = (float*)d_out;
    float* out_node = out;                                   // [N, 16]
    float* out_edge = out + (size_t)NN * ONODE;              // [E, 4]
    float* out_h    = out_edge + (size_t)EE * OEDGE;         // [N, 256]

    void *p_xp, *p_h1, *p_ts;
    cudaGetSymbolAddress(&p_xp, g_xp);
    cudaGetSymbolAddress(&p_h1, g_h1);
    cudaGetSymbolAddress(&p_ts, g_ts);

    const int TB = 256;
    dim3 gProj(HD / 128, (NN + 127) / 128);                  // 2 x 391
    dim3 gTd(1024 / 128, (NN + 127) / 128);                  // 8 x 391
    int gNode = (NN + TB - 1) / TB;
    int gEdge = (EE + TB - 1) / TB;
    int gWarpN = (NN * 32 + TB - 1) / TB;                    // warp-per-node grids

    // ---- build dst-sorted CSR (once per launch) ----
    k_zero<<<gNode, TB>>>();
    k_hist<<<gEdge, TB>>>(ei);
    k_scan1<<<SCAN_B, 256>>>();
    k_scan2<<<1, 256>>>();
    k_scan3<<<gNode, TB>>>();
    k_scatter<<<gEdge, TB>>>(ei);

    // ---- layer 1 ----
    k_gemm_tc<<<gProj, TB>>>(x, W1, (float*)p_xp, NN, HD, INCH);
    k_attn<<<gWarpN, TB>>>((const float*)p_xp, as1, ad1);
    k_gat<<<gWarpN, TB>>>((const float*)p_xp, b1, (float*)p_h1);

    // ---- layer 2 ----
    k_gemm_tc<<<gProj, TB>>>((const float*)p_h1, W2, (float*)p_xp, NN, HD, HD);
    k_attn<<<gWarpN, TB>>>((const float*)p_xp, as2, ad2);
    k_gat<<<gWarpN, TB>>>((const float*)p_xp, b2, out_h);

    // ---- heads ----
    k_nodepred<<<(NN + 15) / 16, TB>>>(out_h, Wn, bn, out_node);
    k_gemm_tc<<<gTd, TB>>>(out_h, Wb, (float*)p_ts, NN, 1024, HD);  // td = h @ Wb^T
    k_bilin<<<gWarpN, TB>>>(out_h, bb, out_edge);
}